// round 9
// baseline (speedup 1.0000x reference)
#include <cuda_runtime.h>
#include <cuda_bf16.h>
#include <float.h>
#include <math.h>

// ---------------------------------------------------------------------------
// MEATransformer: top-3 retrieval over 500K cosine sims + tiny 2-layer
// transformer (768 seqs x 3 tokens x 256) + logits/retrieval mix.
// Round 8: sims kernel rebuilt around crossbar economics:
//   - q tile TRANSPOSED in smem -> 2 broadcast LDS.128 per d (was 4 LDS.32)
//   - 8 query rows per thread (128q x 128c tile) -> half the w-bytes per FMA
//   - grid (148,2), 1 CTA/SM, launch_bounds(256,1), reg-prefetch double buffer
// Tail unchanged (proven).
// ---------------------------------------------------------------------------

#define NN       500000
#define DD       256
#define BB       256
#define KK       3
#define NLAB     12
#define CT       128            // columns per tile in sims kernel
#define NTILES   3907           // ceil(500000/128)
#define GX       148            // sims gridDim.x (partials width)
#define NSEQ     768            // B*K
#define MROWS    2304           // NSEQ*3 token rows

#define QT_STRIDE 132           // transposed q row stride (floats), 16B-aligned
#define SIMS_SMEM_FLOATS (DD * QT_STRIDE + 2 * 32 * CT)
#define SIMS_SMEM_BYTES  (SIMS_SMEM_FLOATS * 4)   // 167936 B

// ---------------- device scratch (no cudaMalloc allowed) -------------------
__device__ float g_qn   [BB * DD];
__device__ float g_pv   [BB * GX * 3];
__device__ int   g_pi   [BB * GX * 3];
__device__ float g_score[NSEQ];
__device__ int   g_idx  [NSEQ];
__device__ int   g_lab  [NSEQ];
__device__ float g_H    [MROWS * DD];
__device__ float g_Qb   [MROWS * DD];
__device__ float g_Kb   [MROWS * DD];
__device__ float g_Vb   [MROWS * DD];
__device__ float g_Ab   [MROWS * DD];
__device__ float g_x    [NSEQ * DD];

// ---------------- f32x2 helpers ---------------------------------------------
__device__ __forceinline__ unsigned long long bcast2(float v) {
    unsigned long long r;
    asm("mov.b64 %0, {%1,%1};" : "=l"(r) : "f"(v));
    return r;
}
__device__ __forceinline__ void unpack2(unsigned long long v, float& lo, float& hi) {
    asm("mov.b64 {%0,%1}, %2;" : "=f"(lo), "=f"(hi) : "l"(v));
}
__device__ __forceinline__ void ffma2(unsigned long long& d,
                                      unsigned long long a,
                                      unsigned long long b) {
    asm("fma.rn.f32x2 %0, %1, %2, %0;" : "+l"(d) : "l"(a), "l"(b));
}

// ---------------- top-3 helpers ----------------------------------------------
__device__ __forceinline__ bool better(float v1, int i1, float v2, int i2) {
    return (v1 > v2) || (v1 == v2 && i1 < i2);   // jax top_k: ties -> lower idx
}
__device__ __forceinline__ void ins3(float v, int i,
                                     float& v0, int& i0,
                                     float& v1, int& i1,
                                     float& v2, int& i2) {
    if (better(v, i, v2, i2)) {
        if (better(v, i, v1, i1)) {
            v2 = v1; i2 = i1;
            if (better(v, i, v0, i0)) { v1 = v0; i1 = i0; v0 = v; i0 = i; }
            else                      { v1 = v;  i1 = i; }
        } else { v2 = v; i2 = i; }
    }
}
__device__ __forceinline__ void merge3(float& a0, int& x0, float& a1, int& x1,
                                       float& a2, int& x2,
                                       float b0, int y0, float b1, int y1,
                                       float b2, int y2) {
    float o0, o1, o2; int p0, p1, p2;
    if (better(a0, x0, b0, y0)) { o0 = a0; p0 = x0; a0 = a1; x0 = x1; a1 = a2; x1 = x2; a2 = -FLT_MAX; x2 = 0x7fffffff; }
    else                        { o0 = b0; p0 = y0; b0 = b1; y0 = y1; b1 = b2; y1 = y2; b2 = -FLT_MAX; y2 = 0x7fffffff; }
    if (better(a0, x0, b0, y0)) { o1 = a0; p1 = x0; a0 = a1; x0 = x1; }
    else                        { o1 = b0; p1 = y0; b0 = b1; y0 = y1; }
    if (better(a0, x0, b0, y0)) { o2 = a0; p2 = x0; }
    else                        { o2 = b0; p2 = y0; }
    a0 = o0; x0 = p0; a1 = o1; x1 = p1; a2 = o2; x2 = p2;
}

// ---------------- kernel 1: normalize queries -------------------------------
__global__ void normalize_kernel(const float* __restrict__ q) {
    __shared__ float ws[8];
    int b = blockIdx.x, t = threadIdx.x;
    float v = q[b * DD + t];
    float s = v * v;
    #pragma unroll
    for (int o = 16; o; o >>= 1) s += __shfl_xor_sync(0xffffffffu, s, o);
    if ((t & 31) == 0) ws[t >> 5] = s;
    __syncthreads();
    float tot = 0.f;
    #pragma unroll
    for (int w = 0; w < 8; w++) tot += ws[w];
    g_qn[b * DD + t] = v / sqrtf(tot);
}

// ---------------- kernel 2: sims GEMM + streaming top-3 ---------------------
// 256 threads (16 tx x 16 ty); tile 128 queries x 128 columns; micro-tile
// 8 rows x 8 cols via f32x2. q tile resident TRANSPOSED in smem (one-time).
// w chunks double-buffered: LDG.128 prefetch into regs overlaps compute,
// STS at stage top, ONE __syncthreads per stage.
extern __shared__ float s_dyn[];
__global__ void __launch_bounds__(256, 1)
sims_topk_kernel(const float* __restrict__ w) {
    float* qt  = s_dyn;                    // [DD][QT_STRIDE] transposed q
    float* wsm = s_dyn + DD * QT_STRIDE;   // 2 x 32 x 128 floats

    const int tid = threadIdx.x;
    const int tx = tid & 15, ty = tid >> 4;
    const int ty8 = ty * 8;
    const int qrow0 = blockIdx.y * 128;

    // ---- one-time transposed q load: qt[d][r] = qn[qrow0+r][d] ----
    for (int r = 0; r < 128; r++)
        qt[tid * QT_STRIDE + r] = g_qn[(qrow0 + r) * DD + tid];

    const int ntiles_mine = (NTILES - blockIdx.x + GX - 1) / GX;

    float tv[8][3]; int ti3[8][3];
    #pragma unroll
    for (int r = 0; r < 8; r++)
        #pragma unroll
        for (int j = 0; j < 3; j++) { tv[r][j] = -FLT_MAX; ti3[r][j] = 0x7fffffff; }

    float4 wr[4];   // prefetch registers for next w stage

    auto ldg_stage = [&](int t, int dk) {
        const int col0 = t * CT;
        #pragma unroll
        for (int j = 0; j < 4; j++) {
            int id = tid + j * 256;
            int r = id >> 5, c4 = id & 31;
            int col = col0 + c4 * 4;
            if (col < NN)
                wr[j] = *(const float4*)(w + (long)(dk * 32 + r) * NN + col);
            else
                wr[j] = make_float4(0.f, 0.f, 0.f, 0.f);
        }
    };
    auto sts_stage = [&](int buf) {
        #pragma unroll
        for (int j = 0; j < 4; j++) {
            int id = tid + j * 256;
            int r = id >> 5, c4 = id & 31;
            *(float4*)(wsm + buf * (32 * CT) + r * CT + c4 * 4) = wr[j];
        }
    };

    ldg_stage(blockIdx.x, 0);   // prologue

    int t = blockIdx.x;
    int stage = 0;
    for (int ti = 0; ti < ntiles_mine; ti++, t += GX) {
        const int col0 = t * CT;
        unsigned long long acc[8][4];
        #pragma unroll
        for (int r = 0; r < 8; r++)
            #pragma unroll
            for (int p = 0; p < 4; p++) acc[r][p] = 0ull;

        for (int dk = 0; dk < 8; dk++, stage++) {
            const int buf = stage & 1;
            sts_stage(buf);
            __syncthreads();   // STS visible; (induction) compute of stage-2 done
            if (dk < 7)                      ldg_stage(t, dk + 1);
            else if (ti + 1 < ntiles_mine)   ldg_stage(t + GX, 0);

            const float* wsf = wsm + buf * (32 * CT);
            const float* qd  = qt + (dk * 32) * QT_STRIDE + ty8;
            #pragma unroll
            for (int d = 0; d < 32; d++) {
                const ulonglong2 a = *(const ulonglong2*)(wsf + d * CT + tx * 4);
                const ulonglong2 b = *(const ulonglong2*)(wsf + d * CT + 64 + tx * 4);
                const float4 qA = *(const float4*)(qd + d * QT_STRIDE);
                const float4 qB = *(const float4*)(qd + d * QT_STRIDE + 4);
                unsigned long long qv;
                qv = bcast2(qA.x);
                ffma2(acc[0][0], qv, a.x); ffma2(acc[0][1], qv, a.y);
                ffma2(acc[0][2], qv, b.x); ffma2(acc[0][3], qv, b.y);
                qv = bcast2(qA.y);
                ffma2(acc[1][0], qv, a.x); ffma2(acc[1][1], qv, a.y);
                ffma2(acc[1][2], qv, b.x); ffma2(acc[1][3], qv, b.y);
                qv = bcast2(qA.z);
                ffma2(acc[2][0], qv, a.x); ffma2(acc[2][1], qv, a.y);
                ffma2(acc[2][2], qv, b.x); ffma2(acc[2][3], qv, b.y);
                qv = bcast2(qA.w);
                ffma2(acc[3][0], qv, a.x); ffma2(acc[3][1], qv, a.y);
                ffma2(acc[3][2], qv, b.x); ffma2(acc[3][3], qv, b.y);
                qv = bcast2(qB.x);
                ffma2(acc[4][0], qv, a.x); ffma2(acc[4][1], qv, a.y);
                ffma2(acc[4][2], qv, b.x); ffma2(acc[4][3], qv, b.y);
                qv = bcast2(qB.y);
                ffma2(acc[5][0], qv, a.x); ffma2(acc[5][1], qv, a.y);
                ffma2(acc[5][2], qv, b.x); ffma2(acc[5][3], qv, b.y);
                qv = bcast2(qB.z);
                ffma2(acc[6][0], qv, a.x); ffma2(acc[6][1], qv, a.y);
                ffma2(acc[6][2], qv, b.x); ffma2(acc[6][3], qv, b.y);
                qv = bcast2(qB.w);
                ffma2(acc[7][0], qv, a.x); ffma2(acc[7][1], qv, a.y);
                ffma2(acc[7][2], qv, b.x); ffma2(acc[7][3], qv, b.y);
            }
        }
        // streaming top-3 insertion
        // acc[rr][0] -> cols col0+tx*4 +0/+1 ; acc[rr][1] -> +2/+3
        // acc[rr][2] -> cols col0+64+tx*4 +0/+1 ; acc[rr][3] -> +2/+3
        #pragma unroll
        for (int rr = 0; rr < 8; rr++) {
            #pragma unroll
            for (int p = 0; p < 4; p++) {
                float lo, hi;
                unpack2(acc[rr][p], lo, hi);
                int grp = p >> 1;
                int c0 = col0 + grp * 64 + tx * 4 + (p & 1) * 2;
                if (c0 < NN)
                    ins3(lo, c0, tv[rr][0], ti3[rr][0], tv[rr][1], ti3[rr][1], tv[rr][2], ti3[rr][2]);
                if (c0 + 1 < NN)
                    ins3(hi, c0 + 1, tv[rr][0], ti3[rr][0], tv[rr][1], ti3[rr][1], tv[rr][2], ti3[rr][2]);
            }
        }
    }

    #pragma unroll
    for (int rr = 0; rr < 8; rr++) {
        #pragma unroll
        for (int off = 8; off >= 1; off >>= 1) {
            float b0 = __shfl_xor_sync(0xffffffffu, tv[rr][0], off, 16);
            float b1 = __shfl_xor_sync(0xffffffffu, tv[rr][1], off, 16);
            float b2 = __shfl_xor_sync(0xffffffffu, tv[rr][2], off, 16);
            int   y0 = __shfl_xor_sync(0xffffffffu, ti3[rr][0], off, 16);
            int   y1 = __shfl_xor_sync(0xffffffffu, ti3[rr][1], off, 16);
            int   y2 = __shfl_xor_sync(0xffffffffu, ti3[rr][2], off, 16);
            merge3(tv[rr][0], ti3[rr][0], tv[rr][1], ti3[rr][1], tv[rr][2], ti3[rr][2],
                   b0, y0, b1, y1, b2, y2);
        }
        if (tx == 0) {
            int q = qrow0 + ty8 + rr;
            int base = (q * GX + blockIdx.x) * 3;
            #pragma unroll
            for (int j = 0; j < 3; j++) { g_pv[base + j] = tv[rr][j]; g_pi[base + j] = ti3[rr][j]; }
        }
    }
}

// ---------------- kernel 3: merge partial top-3 per query -------------------
// 160 threads (5 warps); lanes t >= GX hold neutral values.
__global__ void topk_merge_kernel(const int* __restrict__ label) {
    __shared__ float sv[5][3];
    __shared__ int   si[5][3];
    int b = blockIdx.x, t = threadIdx.x;
    float v0 = -FLT_MAX, v1 = -FLT_MAX, v2 = -FLT_MAX;
    int   i0 = 0x7fffffff, i1 = 0x7fffffff, i2 = 0x7fffffff;
    if (t < GX) {
        int base = (b * GX + t) * 3;
        v0 = g_pv[base];     i0 = g_pi[base];
        v1 = g_pv[base + 1]; i1 = g_pi[base + 1];
        v2 = g_pv[base + 2]; i2 = g_pi[base + 2];
    }
    #pragma unroll
    for (int off = 16; off >= 1; off >>= 1) {
        float b0 = __shfl_xor_sync(0xffffffffu, v0, off);
        float b1 = __shfl_xor_sync(0xffffffffu, v1, off);
        float b2 = __shfl_xor_sync(0xffffffffu, v2, off);
        int   y0 = __shfl_xor_sync(0xffffffffu, i0, off);
        int   y1 = __shfl_xor_sync(0xffffffffu, i1, off);
        int   y2 = __shfl_xor_sync(0xffffffffu, i2, off);
        merge3(v0, i0, v1, i1, v2, i2, b0, y0, b1, y1, b2, y2);
    }
    int warp = t >> 5;
    if ((t & 31) == 0) { sv[warp][0] = v0; si[warp][0] = i0; sv[warp][1] = v1; si[warp][1] = i1; sv[warp][2] = v2; si[warp][2] = i2; }
    __syncthreads();
    if (t == 0) {
        float f0 = -FLT_MAX, f1 = -FLT_MAX, f2 = -FLT_MAX;
        int   j0 = 0x7fffffff, j1 = 0x7fffffff, j2 = 0x7fffffff;
        for (int wp = 0; wp < 5; wp++)
            for (int e = 0; e < 3; e++)
                ins3(sv[wp][e], si[wp][e], f0, j0, f1, j1, f2, j2);
        float fv[3] = {f0, f1, f2}; int fi[3] = {j0, j1, j2};
        for (int k = 0; k < 3; k++) {
            g_score[b * 3 + k] = fv[k];
            g_idx[b * 3 + k]   = fi[k];
            g_lab[b * 3 + k]   = label[fi[k]];
        }
    }
}

// ---------------- kernel 4: build H (gather) ---------------------------------
__global__ void build_h_kernel(const float* __restrict__ queries,
                               const float* __restrict__ w) {
    int s = blockIdx.x;       // 0..767
    int d = threadIdx.x;      // 0..255
    int b = s / KK;
    int lab = g_lab[s];
    float score = g_score[s];
    int idx = g_idx[s];
    float* Hrow = &g_H[s * 3 * DD];
    Hrow[d]           = (d == lab) ? score : 0.f;   // CLS token
    Hrow[DD + d]      = queries[b * DD + d];        // query token
    Hrow[2 * DD + d]  = w[d * NN + idx];            // retrieved token
}

// ---------------- tail: fused Q/K/V matvec, 16 rows per block ----------------
__global__ void qkv_kernel(const float* __restrict__ Wq, const float* __restrict__ bq,
                           const float* __restrict__ Wk, const float* __restrict__ bk,
                           const float* __restrict__ Wv, const float* __restrict__ bv) {
    __shared__ float h[16][DD];
    int r0 = blockIdx.x * 16, t = threadIdx.x;
    #pragma unroll
    for (int i = 0; i < 16; i++) h[i][t] = g_H[(r0 + i) * DD + t];
    __syncthreads();
    float aq[16], ak[16], av[16];
    #pragma unroll
    for (int i = 0; i < 16; i++) { aq[i] = bq[t]; ak[i] = bk[t]; av[i] = bv[t]; }
    for (int d = 0; d < DD; d++) {
        float wq = Wq[d * DD + t], wk = Wk[d * DD + t], wv = Wv[d * DD + t];
        #pragma unroll
        for (int i = 0; i < 16; i++) {
            float hv = h[i][d];
            aq[i] += hv * wq;
            ak[i] += hv * wk;
            av[i] += hv * wv;
        }
    }
    #pragma unroll
    for (int i = 0; i < 16; i++) {
        g_Qb[(r0 + i) * DD + t] = aq[i];
        g_Kb[(r0 + i) * DD + t] = ak[i];
        g_Vb[(r0 + i) * DD + t] = av[i];
    }
}

// ---------------- attention: scalar 3x3 per sequence -------------------------
__global__ void attn_kernel() {
    __shared__ float q[3][DD], k[3][DD], v[3][DD], a[9];
    int s = blockIdx.x, t = threadIdx.x;
    int base = s * 3 * DD;
    #pragma unroll
    for (int i = 0; i < 3; i++) {
        q[i][t] = g_Qb[base + i * DD + t];
        k[i][t] = g_Kb[base + i * DD + t];
        v[i][t] = g_Vb[base + i * DD + t];
    }
    __syncthreads();
    if (t < 9) {
        int i = t / 3, j = t % 3;
        float acc = 0.f;
        for (int d = 0; d < DD; d++) acc += q[i][d] * k[j][d];
        a[t] = acc * 0.125f;           // / sqrt(dk), dk = 64
    }
    __syncthreads();
    if (t < 3) {
        float m0 = fmaxf(a[t*3], fmaxf(a[t*3+1], a[t*3+2]));
        float e0 = expf(a[t*3]   - m0);
        float e1 = expf(a[t*3+1] - m0);
        float e2 = expf(a[t*3+2] - m0);
        float inv = 1.f / (e0 + e1 + e2);
        a[t*3] = e0 * inv; a[t*3+1] = e1 * inv; a[t*3+2] = e2 * inv;
    }
    __syncthreads();
    #pragma unroll
    for (int i = 0; i < 3; i++)
        g_Ab[base + i * DD + t] = a[i*3] * v[0][t] + a[i*3+1] * v[1][t] + a[i*3+2] * v[2][t];
}

// ---------------- O projection: H = Ab @ Wo + bo, 16 rows per block ----------
__global__ void oproj_kernel(const float* __restrict__ Wo, const float* __restrict__ bo) {
    __shared__ float h[16][DD];
    int r0 = blockIdx.x * 16, t = threadIdx.x;
    #pragma unroll
    for (int i = 0; i < 16; i++) h[i][t] = g_Ab[(r0 + i) * DD + t];
    __syncthreads();
    float ao[16];
    #pragma unroll
    for (int i = 0; i < 16; i++) ao[i] = bo[t];
    for (int d = 0; d < DD; d++) {
        float wo = Wo[d * DD + t];
        #pragma unroll
        for (int i = 0; i < 16; i++) ao[i] += h[i][d] * wo;
    }
    #pragma unroll
    for (int i = 0; i < 16; i++) g_H[(r0 + i) * DD + t] = ao[i];
}

// ---------------- dense on CLS rows: x = tanh(H[:,0,:] @ W + b) --------------
__global__ void dense_kernel(const float* __restrict__ W, const float* __restrict__ b) {
    __shared__ float h[DD];
    int s = blockIdx.x, t = threadIdx.x;
    h[t] = g_H[s * 3 * DD + t];       // CLS row
    __syncthreads();
    float acc = b[t];
    for (int d = 0; d < DD; d++) acc += h[d] * W[d * DD + t];
    g_x[s * DD + t] = tanhf(acc);
}

// ---------------- final: logits mean + retrieval mix -------------------------
__global__ void final_kernel(const float* __restrict__ out_w,
                             const float* __restrict__ out_b,
                             float* __restrict__ out) {
    __shared__ float lg[36];
    int b = blockIdx.x, t = threadIdx.x;   // 36 threads
    int k = t / NLAB, l = t % NLAB;
    float acc = out_b[l];
    const float* x = &g_x[(b * 3 + k) * DD];
    for (int d = 0; d < DD; d++) acc += x[d] * out_w[d * NLAB + l];
    lg[t] = acc;
    __syncthreads();
    if (t < NLAB) {
        float mean = (lg[t] + lg[NLAB + t] + lg[2 * NLAB + t]) * (1.f / 3.f);
        int l0 = g_lab[b * 3], l1 = g_lab[b * 3 + 1], l2 = g_lab[b * 3 + 2];
        float cnt = (float)((l0 == t) + (l1 == t) + (l2 == t));
        out[b * NLAB + t] = 0.5f * mean + 0.5f * (cnt * (1.f / 3.f));
    }
}

// ---------------- launcher ---------------------------------------------------
extern "C" void kernel_launch(void* const* d_in, const int* in_sizes, int n_in,
                              void* d_out, int out_size) {
    const float* queries = (const float*)d_in[0];
    const float* weight  = (const float*)d_in[1];
    const int*   label   = (const int*)  d_in[2];
    const float* Wq      = (const float*)d_in[3];
    const float* bq      = (const float*)d_in[4];
    const float* Wk      = (const float*)d_in[5];
    const float* bk      = (const float*)d_in[6];
    const float* Wv      = (const float*)d_in[7];
    const float* bv      = (const float*)d_in[8];
    const float* Wo      = (const float*)d_in[9];
    const float* bo      = (const float*)d_in[10];
    const float* dense_w = (const float*)d_in[11];
    const float* dense_b = (const float*)d_in[12];
    const float* out_w   = (const float*)d_in[13];
    const float* out_b   = (const float*)d_in[14];
    float* out = (float*)d_out;

    static bool attr_set = false;
    if (!attr_set) {
        cudaFuncSetAttribute(sims_topk_kernel,
                             cudaFuncAttributeMaxDynamicSharedMemorySize,
                             SIMS_SMEM_BYTES);
        attr_set = true;
    }

    normalize_kernel<<<BB, DD>>>(queries);
    sims_topk_kernel<<<dim3(GX, 2), 256, SIMS_SMEM_BYTES>>>(weight);
    topk_merge_kernel<<<BB, 160>>>(label);
    build_h_kernel<<<NSEQ, DD>>>(queries, weight);

    for (int l = 0; l < 2; l++) {
        qkv_kernel<<<MROWS / 16, DD>>>(Wq + l * DD * DD, bq + l * DD,
                                       Wk + l * DD * DD, bk + l * DD,
                                       Wv + l * DD * DD, bv + l * DD);
        attn_kernel<<<NSEQ, DD>>>();
        oproj_kernel<<<MROWS / 16, DD>>>(Wo + l * DD * DD, bo + l * DD);
    }
    dense_kernel<<<NSEQ, DD>>>(dense_w, dense_b);
    final_kernel<<<BB, 36>>>(out_w, out_b, out);
}

// round 11
// speedup vs baseline: 2.1294x; 2.1294x over previous
#include <cuda_runtime.h>
#include <cuda_bf16.h>
#include <float.h>
#include <math.h>
#include <stdint.h>

// ---------------------------------------------------------------------------
// MEATransformer. Round 10: tcgen05 unavailable (harness compiles via
// compute_103 PTX). Sims via mma.sync.m16n8k16 bf16 HMMA, single-pass bf16
// sieve (top-4/CTA/row) + exact fp32 rescore of MMA-top-16 candidates.
// Fragment-packed B in gmem -> contiguous LDS.128, no ldmatrix, no swizzle.
// ---------------------------------------------------------------------------

#define NN       500000
#define DD       256
#define BB       256
#define KK       3
#define NLAB     12
#define NSEQ     768
#define MROWS    2304

#define NCHUNK   15625          // 500000/32
#define NCTA     148
#define NCAND    (NCTA * 4)     // 592 candidates per query
#define NTFRAG   62500          // 500000/8 n-tiles of 8

// ---------------- device scratch --------------------------------------------
__device__ float          g_qn  [BB * DD];
__device__ __nv_bfloat16  g_qhi [BB * DD];
__device__ uint4          g_wfrag[(size_t)NTFRAG * 8 * 32 / 2];  // 16M uint4? see note
// NOTE: layout is [T][ks2(8)][lane(32)] of uint4 = NTFRAG*8*32 uint4 entries.
// NTFRAG*8*32 = 16,000,000 uint4 = 256 MB. (Divide-by-2 above would be wrong;
// declare exact size:)
#define WFRAG_ENTRIES ((size_t)NTFRAG * 8 * 32)
__device__ uint4          g_wfrag_main[WFRAG_ENTRIES];

__device__ float g_pv   [BB * NCAND];
__device__ int   g_pi   [BB * NCAND];
__device__ float g_score[NSEQ];
__device__ int   g_idx  [NSEQ];
__device__ int   g_lab  [NSEQ];
__device__ float g_H    [MROWS * DD];
__device__ float g_Qb   [MROWS * DD];
__device__ float g_Kb   [MROWS * DD];
__device__ float g_Vb   [MROWS * DD];
__device__ float g_Ab   [MROWS * DD];
__device__ float g_x    [NSEQ * DD];

// ---------------- helpers ----------------------------------------------------
__device__ __forceinline__ uint32_t pack_bf16x2(float lo, float hi) {
    __nv_bfloat162 p = __floats2bfloat162_rn(lo, hi);   // p.x = lo, p.y = hi
    uint32_t r;
    memcpy(&r, &p, 4);
    return r;
}

__device__ __forceinline__ void mma_bf16(float& d0, float& d1, float& d2, float& d3,
                                         uint32_t a0, uint32_t a1, uint32_t a2, uint32_t a3,
                                         uint32_t b0, uint32_t b1) {
    asm volatile("mma.sync.aligned.m16n8k16.row.col.f32.bf16.bf16.f32 "
                 "{%0,%1,%2,%3}, {%4,%5,%6,%7}, {%8,%9}, {%0,%1,%2,%3};"
                 : "+f"(d0), "+f"(d1), "+f"(d2), "+f"(d3)
                 : "r"(a0), "r"(a1), "r"(a2), "r"(a3), "r"(b0), "r"(b1));
}

__device__ __forceinline__ bool better(float v1, int i1, float v2, int i2) {
    return (v1 > v2) || (v1 == v2 && i1 < i2);   // jax top_k tie-break
}
__device__ __forceinline__ void ins3(float v, int i,
                                     float& v0, int& i0, float& v1, int& i1,
                                     float& v2, int& i2) {
    if (better(v, i, v2, i2)) {
        if (better(v, i, v1, i1)) {
            v2 = v1; i2 = i1;
            if (better(v, i, v0, i0)) { v1 = v0; i1 = i0; v0 = v; i0 = i; }
            else                      { v1 = v;  i1 = i; }
        } else { v2 = v; i2 = i; }
    }
}
__device__ __forceinline__ void ins4(float v, int i,
                                     float& t0, int& i0, float& t1, int& i1,
                                     float& t2, int& i2, float& t3, int& i3) {
    if (v <= t3) return;
    if (v > t1) {
        if (v > t0) { t3 = t2; i3 = i2; t2 = t1; i2 = i1; t1 = t0; i1 = i0; t0 = v; i0 = i; }
        else        { t3 = t2; i3 = i2; t2 = t1; i2 = i1; t1 = v;  i1 = i; }
    } else {
        if (v > t2) { t3 = t2; i3 = i2; t2 = v; i2 = i; }
        else        { t3 = v;  i3 = i; }
    }
}

// ---------------- kernel 1: normalize queries (+ bf16 copy) ------------------
__global__ void normalize_kernel(const float* __restrict__ q) {
    __shared__ float ws[8];
    int b = blockIdx.x, t = threadIdx.x;
    float v = q[b * DD + t];
    float s = v * v;
    #pragma unroll
    for (int o = 16; o; o >>= 1) s += __shfl_xor_sync(0xffffffffu, s, o);
    if ((t & 31) == 0) ws[t >> 5] = s;
    __syncthreads();
    float tot = 0.f;
    #pragma unroll
    for (int w = 0; w < 8; w++) tot += ws[w];
    float qn = v / sqrtf(tot);
    g_qn [b * DD + t] = qn;
    g_qhi[b * DD + t] = __float2bfloat16(qn);
}

// ---------------- kernel 2: w[d][n] fp32 -> fragment-packed bf16 -------------
// Fragment layout (uint4 index): (T*8 + ks2)*32 + lane, T = n/8, ks2 = k/32.
// uint4 = {b0(ks=2*ks2), b1(ks=2*ks2), b0(ks=2*ks2+1), b1(ks=2*ks2+1)} where
// b0 = bf16x2 of w at k = ks*16 + (lane&3)*2 (+1), b1 = same + 8, n = 8T+(lane>>2).
__global__ void convert_w_kernel(const float* __restrict__ w) {
    __shared__ float stage[64][65];
    const int n0 = blockIdx.x * 64;
    const int tid = threadIdx.x;
    for (int kp = 0; kp < 4; kp++) {
        #pragma unroll
        for (int j = 0; j < 16; j++) {
            int lin = tid + j * 256;
            int kk = lin >> 6, nn = lin & 63;
            stage[kk][nn] = (n0 + nn < NN)
                          ? w[(size_t)(kp * 64 + kk) * NN + n0 + nn] : 0.f;
        }
        __syncthreads();
        #pragma unroll
        for (int i = 0; i < 2; i++) {
            int u = tid + i * 256;
            int lane = u & 31;
            int ks2loc = (u >> 5) & 1;
            int Tloc = u >> 6;                 // 0..7
            int Tglob = blockIdx.x * 8 + Tloc;
            if (Tglob < NTFRAG) {
                int n_loc = Tloc * 8 + (lane >> 2);
                int kbase = (lane & 3) * 2;
                uint32_t r[4];
                #pragma unroll
                for (int rr = 0; rr < 4; rr++) {
                    int k_local = (ks2loc * 2 + (rr >> 1)) * 16 + kbase + (rr & 1) * 8;
                    r[rr] = pack_bf16x2(stage[k_local][n_loc], stage[k_local + 1][n_loc]);
                }
                int ks2 = kp * 2 + ks2loc;
                g_wfrag_main[((size_t)Tglob * 8 + ks2) * 32 + lane] =
                    make_uint4(r[0], r[1], r[2], r[3]);
            }
        }
        __syncthreads();
    }
}

// ---------------- kernel 3: sims via mma.sync + streaming top-4 sieve --------
// 148 CTAs x 512 threads (16 warps). Warp w owns q rows [16w, 16w+16).
// CTA bx streams 32-col chunks c = bx, bx+148, ... A fragments persistent in
// registers; B tile (16KB) double-buffered via reg-prefetch, 1 barrier/tile.
__global__ void __launch_bounds__(512, 1) sims_mma_kernel() {
    __shared__ uint4 sB[2][1024];
    const int tid = threadIdx.x;
    const int wid = tid >> 5, lane = tid & 31;
    const int g = lane >> 2, qk = lane & 3;
    const int bx = blockIdx.x;
    const int row0 = wid * 16 + g;

    // ---- persistent A fragments: 16 ksteps x 4 regs ----
    uint32_t Af[16][4];
    const uint32_t* qh = (const uint32_t*)g_qhi;
    #pragma unroll
    for (int ks = 0; ks < 16; ks++) {
        int k0 = ks * 16 + qk * 2;
        Af[ks][0] = qh[(row0 * DD + k0) >> 1];
        Af[ks][1] = qh[((row0 + 8) * DD + k0) >> 1];
        Af[ks][2] = qh[(row0 * DD + k0 + 8) >> 1];
        Af[ks][3] = qh[((row0 + 8) * DD + k0 + 8) >> 1];
    }

    const int ntiles = (NCHUNK - bx + NCTA - 1) / NCTA;

    float va0 = -FLT_MAX, va1 = -FLT_MAX, va2 = -FLT_MAX, va3 = -FLT_MAX;
    int   ja0 = 0x7fffffff, ja1 = 0x7fffffff, ja2 = 0x7fffffff, ja3 = 0x7fffffff;
    float vb0 = -FLT_MAX, vb1 = -FLT_MAX, vb2 = -FLT_MAX, vb3 = -FLT_MAX;
    int   jb0 = 0x7fffffff, jb1 = 0x7fffffff, jb2 = 0x7fffffff, jb3 = 0x7fffffff;

    uint4 wr0, wr1;
    {   // prologue prefetch
        const uint4* src = g_wfrag_main + (size_t)bx * 1024;
        wr0 = src[tid]; wr1 = src[tid + 512];
    }

    for (int t = 0; t < ntiles; t++) {
        const int buf = t & 1;
        sB[buf][tid] = wr0;
        sB[buf][tid + 512] = wr1;
        __syncthreads();
        if (t + 1 < ntiles) {
            const uint4* src = g_wfrag_main + (size_t)(bx + (t + 1) * NCTA) * 1024;
            wr0 = src[tid]; wr1 = src[tid + 512];
        }
        const int colbase = (bx + t * NCTA) * 32 + qk * 2;
        #pragma unroll
        for (int nt = 0; nt < 4; nt++) {
            float d0 = 0.f, d1 = 0.f, d2 = 0.f, d3 = 0.f;
            #pragma unroll
            for (int ks2 = 0; ks2 < 8; ks2++) {
                uint4 bf = sB[buf][(nt * 8 + ks2) * 32 + lane];
                mma_bf16(d0, d1, d2, d3,
                         Af[2*ks2][0], Af[2*ks2][1], Af[2*ks2][2], Af[2*ks2][3],
                         bf.x, bf.y);
                mma_bf16(d0, d1, d2, d3,
                         Af[2*ks2+1][0], Af[2*ks2+1][1], Af[2*ks2+1][2], Af[2*ks2+1][3],
                         bf.z, bf.w);
            }
            int c0 = colbase + nt * 8;
            ins4(d0, c0,     va0, ja0, va1, ja1, va2, ja2, va3, ja3);
            ins4(d1, c0 + 1, va0, ja0, va1, ja1, va2, ja2, va3, ja3);
            ins4(d2, c0,     vb0, jb0, vb1, jb1, vb2, jb2, vb3, jb3);
            ins4(d3, c0 + 1, vb0, jb0, vb1, jb1, vb2, jb2, vb3, jb3);
        }
    }

    // ---- merge top-4 across the 4 lanes of each quad (width-4 butterflies) --
    #pragma unroll
    for (int m = 1; m <= 2; m <<= 1) {
        float r0 = __shfl_xor_sync(0xffffffffu, va0, m, 4);
        float r1 = __shfl_xor_sync(0xffffffffu, va1, m, 4);
        float r2 = __shfl_xor_sync(0xffffffffu, va2, m, 4);
        float r3 = __shfl_xor_sync(0xffffffffu, va3, m, 4);
        int   s0 = __shfl_xor_sync(0xffffffffu, ja0, m, 4);
        int   s1 = __shfl_xor_sync(0xffffffffu, ja1, m, 4);
        int   s2 = __shfl_xor_sync(0xffffffffu, ja2, m, 4);
        int   s3 = __shfl_xor_sync(0xffffffffu, ja3, m, 4);
        ins4(r0, s0, va0, ja0, va1, ja1, va2, ja2, va3, ja3);
        ins4(r1, s1, va0, ja0, va1, ja1, va2, ja2, va3, ja3);
        ins4(r2, s2, va0, ja0, va1, ja1, va2, ja2, va3, ja3);
        ins4(r3, s3, va0, ja0, va1, ja1, va2, ja2, va3, ja3);
        r0 = __shfl_xor_sync(0xffffffffu, vb0, m, 4);
        r1 = __shfl_xor_sync(0xffffffffu, vb1, m, 4);
        r2 = __shfl_xor_sync(0xffffffffu, vb2, m, 4);
        r3 = __shfl_xor_sync(0xffffffffu, vb3, m, 4);
        s0 = __shfl_xor_sync(0xffffffffu, jb0, m, 4);
        s1 = __shfl_xor_sync(0xffffffffu, jb1, m, 4);
        s2 = __shfl_xor_sync(0xffffffffu, jb2, m, 4);
        s3 = __shfl_xor_sync(0xffffffffu, jb3, m, 4);
        ins4(r0, s0, vb0, jb0, vb1, jb1, vb2, jb2, vb3, jb3);
        ins4(r1, s1, vb0, jb0, vb1, jb1, vb2, jb2, vb3, jb3);
        ins4(r2, s2, vb0, jb0, vb1, jb1, vb2, jb2, vb3, jb3);
        ins4(r3, s3, vb0, jb0, vb1, jb1, vb2, jb2, vb3, jb3);
    }
    if (qk == 0) {
        int base = row0 * NCAND + bx * 4;
        g_pv[base + 0] = va0; g_pi[base + 0] = ja0;
        g_pv[base + 1] = va1; g_pi[base + 1] = ja1;
        g_pv[base + 2] = va2; g_pi[base + 2] = ja2;
        g_pv[base + 3] = va3; g_pi[base + 3] = ja3;
        base = (row0 + 8) * NCAND + bx * 4;
        g_pv[base + 0] = vb0; g_pi[base + 0] = jb0;
        g_pv[base + 1] = vb1; g_pi[base + 1] = jb1;
        g_pv[base + 2] = vb2; g_pi[base + 2] = jb2;
        g_pv[base + 3] = vb3; g_pi[base + 3] = jb3;
    }
}

// ---------------- kernel 4: merge candidates, exact rescore, final top-3 -----
__global__ void merge_rescore_kernel(const float* __restrict__ w,
                                     const int* __restrict__ label) {
    __shared__ float cv[NCAND];
    __shared__ int   ci[NCAND];
    __shared__ float qrow[DD];
    __shared__ float s16v[16];
    __shared__ int   s16i[16];
    int q = blockIdx.x, t = threadIdx.x;
    qrow[t] = g_qn[q * DD + t];
    for (int j = t; j < NCAND; j += 256) {
        cv[j] = g_pv[q * NCAND + j];
        ci[j] = g_pi[q * NCAND + j];
    }
    __syncthreads();
    if (t == 0) {
        float bv[16]; int bi[16];
        #pragma unroll
        for (int k = 0; k < 16; k++) { bv[k] = -FLT_MAX; bi[k] = 0x7fffffff; }
        for (int j = 0; j < NCAND; j++) {
            float v = cv[j]; int ix = ci[j];
            if (better(v, ix, bv[15], bi[15])) {
                int pos = 15;
                for (int k = 14; k >= 0; k--)
                    if (better(v, ix, bv[k], bi[k])) {
                        bv[k + 1] = bv[k]; bi[k + 1] = bi[k]; pos = k;
                    }
                bv[pos] = v; bi[pos] = ix;
            }
        }
        #pragma unroll
        for (int k = 0; k < 16; k++) s16i[k] = bi[k];
    }
    __syncthreads();
    if (t < 16) {
        int idx = s16i[t];
        float acc = 0.f;
        for (int d = 0; d < DD; d++) acc += qrow[d] * w[(size_t)d * NN + idx];
        s16v[t] = acc;
    }
    __syncthreads();
    if (t == 0) {
        float f0 = -FLT_MAX, f1 = -FLT_MAX, f2 = -FLT_MAX;
        int   j0 = 0x7fffffff, j1 = 0x7fffffff, j2 = 0x7fffffff;
        for (int k = 0; k < 16; k++)
            ins3(s16v[k], s16i[k], f0, j0, f1, j1, f2, j2);
        g_score[q * 3 + 0] = f0; g_idx[q * 3 + 0] = j0; g_lab[q * 3 + 0] = label[j0];
        g_score[q * 3 + 1] = f1; g_idx[q * 3 + 1] = j1; g_lab[q * 3 + 1] = label[j1];
        g_score[q * 3 + 2] = f2; g_idx[q * 3 + 2] = j2; g_lab[q * 3 + 2] = label[j2];
    }
}

// ---------------- kernel 5: build H (gather) ---------------------------------
__global__ void build_h_kernel(const float* __restrict__ queries,
                               const float* __restrict__ w) {
    int s = blockIdx.x, d = threadIdx.x;
    int b = s / KK;
    int lab = g_lab[s];
    float score = g_score[s];
    int idx = g_idx[s];
    float* Hrow = &g_H[s * 3 * DD];
    Hrow[d]          = (d == lab) ? score : 0.f;
    Hrow[DD + d]     = queries[b * DD + d];
    Hrow[2 * DD + d] = w[(size_t)d * NN + idx];
}

// ---------------- tail (proven) ----------------------------------------------
__global__ void qkv_kernel(const float* __restrict__ Wq, const float* __restrict__ bq,
                           const float* __restrict__ Wk, const float* __restrict__ bk,
                           const float* __restrict__ Wv, const float* __restrict__ bv) {
    __shared__ float h[16][DD];
    int r0 = blockIdx.x * 16, t = threadIdx.x;
    #pragma unroll
    for (int i = 0; i < 16; i++) h[i][t] = g_H[(r0 + i) * DD + t];
    __syncthreads();
    float aq[16], ak[16], av[16];
    #pragma unroll
    for (int i = 0; i < 16; i++) { aq[i] = bq[t]; ak[i] = bk[t]; av[i] = bv[t]; }
    for (int d = 0; d < DD; d++) {
        float wq = Wq[d * DD + t], wk = Wk[d * DD + t], wv = Wv[d * DD + t];
        #pragma unroll
        for (int i = 0; i < 16; i++) {
            float hv = h[i][d];
            aq[i] += hv * wq; ak[i] += hv * wk; av[i] += hv * wv;
        }
    }
    #pragma unroll
    for (int i = 0; i < 16; i++) {
        g_Qb[(r0 + i) * DD + t] = aq[i];
        g_Kb[(r0 + i) * DD + t] = ak[i];
        g_Vb[(r0 + i) * DD + t] = av[i];
    }
}

__global__ void attn_kernel() {
    __shared__ float q[3][DD], k[3][DD], v[3][DD], a[9];
    int s = blockIdx.x, t = threadIdx.x;
    int base = s * 3 * DD;
    #pragma unroll
    for (int i = 0; i < 3; i++) {
        q[i][t] = g_Qb[base + i * DD + t];
        k[i][t] = g_Kb[base + i * DD + t];
        v[i][t] = g_Vb[base + i * DD + t];
    }
    __syncthreads();
    if (t < 9) {
        int i = t / 3, j = t % 3;
        float acc = 0.f;
        for (int d = 0; d < DD; d++) acc += q[i][d] * k[j][d];
        a[t] = acc * 0.125f;
    }
    __syncthreads();
    if (t < 3) {
        float m0 = fmaxf(a[t*3], fmaxf(a[t*3+1], a[t*3+2]));
        float e0 = expf(a[t*3] - m0), e1 = expf(a[t*3+1] - m0), e2 = expf(a[t*3+2] - m0);
        float inv = 1.f / (e0 + e1 + e2);
        a[t*3] = e0 * inv; a[t*3+1] = e1 * inv; a[t*3+2] = e2 * inv;
    }
    __syncthreads();
    #pragma unroll
    for (int i = 0; i < 3; i++)
        g_Ab[base + i * DD + t] = a[i*3] * v[0][t] + a[i*3+1] * v[1][t] + a[i*3+2] * v[2][t];
}

__global__ void oproj_kernel(const float* __restrict__ Wo, const float* __restrict__ bo) {
    __shared__ float h[16][DD];
    int r0 = blockIdx.x * 16, t = threadIdx.x;
    #pragma unroll
    for (int i = 0; i < 16; i++) h[i][t] = g_Ab[(r0 + i) * DD + t];
    __syncthreads();
    float ao[16];
    #pragma unroll
    for (int i = 0; i < 16; i++) ao[i] = bo[t];
    for (int d = 0; d < DD; d++) {
        float wo = Wo[d * DD + t];
        #pragma unroll
        for (int i = 0; i < 16; i++) ao[i] += h[i][d] * wo;
    }
    #pragma unroll
    for (int i = 0; i < 16; i++) g_H[(r0 + i) * DD + t] = ao[i];
}

__global__ void dense_kernel(const float* __restrict__ W, const float* __restrict__ b) {
    __shared__ float h[DD];
    int s = blockIdx.x, t = threadIdx.x;
    h[t] = g_H[s * 3 * DD + t];
    __syncthreads();
    float acc = b[t];
    for (int d = 0; d < DD; d++) acc += h[d] * W[d * DD + t];
    g_x[s * DD + t] = tanhf(acc);
}

__global__ void final_kernel(const float* __restrict__ out_w,
                             const float* __restrict__ out_b,
                             float* __restrict__ out) {
    __shared__ float lg[36];
    int b = blockIdx.x, t = threadIdx.x;
    int k = t / NLAB, l = t % NLAB;
    float acc = out_b[l];
    const float* x = &g_x[(b * 3 + k) * DD];
    for (int d = 0; d < DD; d++) acc += x[d] * out_w[d * NLAB + l];
    lg[t] = acc;
    __syncthreads();
    if (t < NLAB) {
        float mean = (lg[t] + lg[NLAB + t] + lg[2 * NLAB + t]) * (1.f / 3.f);
        int l0 = g_lab[b * 3], l1 = g_lab[b * 3 + 1], l2 = g_lab[b * 3 + 2];
        float cnt = (float)((l0 == t) + (l1 == t) + (l2 == t));
        out[b * NLAB + t] = 0.5f * mean + 0.5f * (cnt * (1.f / 3.f));
    }
}

// ---------------- launcher ---------------------------------------------------
extern "C" void kernel_launch(void* const* d_in, const int* in_sizes, int n_in,
                              void* d_out, int out_size) {
    const float* queries = (const float*)d_in[0];
    const float* weight  = (const float*)d_in[1];
    const int*   label   = (const int*)  d_in[2];
    const float* Wq      = (const float*)d_in[3];
    const float* bq      = (const float*)d_in[4];
    const float* Wk      = (const float*)d_in[5];
    const float* bk      = (const float*)d_in[6];
    const float* Wv      = (const float*)d_in[7];
    const float* bv      = (const float*)d_in[8];
    const float* Wo      = (const float*)d_in[9];
    const float* bo      = (const float*)d_in[10];
    const float* dense_w = (const float*)d_in[11];
    const float* dense_b = (const float*)d_in[12];
    const float* out_w   = (const float*)d_in[13];
    const float* out_b   = (const float*)d_in[14];
    float* out = (float*)d_out;

    normalize_kernel<<<BB, DD>>>(queries);
    convert_w_kernel<<<(NN + 63) / 64, 256>>>(weight);
    sims_mma_kernel<<<NCTA, 512>>>();
    merge_rescore_kernel<<<BB, 256>>>(weight, label);
    build_h_kernel<<<NSEQ, DD>>>(queries, weight);

    for (int l = 0; l < 2; l++) {
        qkv_kernel<<<MROWS / 16, DD>>>(Wq + l * DD * DD, bq + l * DD,
                                       Wk + l * DD * DD, bk + l * DD,
                                       Wv + l * DD * DD, bv + l * DD);
        attn_kernel<<<NSEQ, DD>>>();
        oproj_kernel<<<MROWS / 16, DD>>>(Wo + l * DD * DD, bo + l * DD);
    }
    dense_kernel<<<NSEQ, DD>>>(dense_w, dense_b);
    final_kernel<<<BB, 36>>>(out_w, out_b, out);
}

// round 12
// speedup vs baseline: 2.4525x; 1.1517x over previous
#include <cuda_runtime.h>
#include <cuda_bf16.h>
#include <float.h>
#include <math.h>
#include <stdint.h>

// ---------------------------------------------------------------------------
// MEATransformer. Round 11: fuse w fp32->bf16 fragment conversion INTO the
// sims MMA kernel (on-the-fly pack, 512MB total DRAM vs 1024MB), and
// parallelize merge_rescore (8-warp top-4 sieve + 8-thread/cand exact rescore).
// Sieve/rescore candidate coverage is a superset of R10 -> identical output.
// ---------------------------------------------------------------------------

#define NN       500000
#define DD       256
#define BB       256
#define KK       3
#define NLAB     12
#define NSEQ     768
#define MROWS    2304

#define NCHUNK   15625          // 500000/32 col-chunks
#define NCTA     148
#define NCAND    (NCTA * 4)     // 592 candidates per query

// ---------------- device scratch --------------------------------------------
__device__ float          g_qn  [BB * DD];
__device__ __nv_bfloat16  g_qhi [BB * DD];
__device__ float g_pv   [BB * NCAND];
__device__ int   g_pi   [BB * NCAND];
__device__ float g_score[NSEQ];
__device__ int   g_idx  [NSEQ];
__device__ int   g_lab  [NSEQ];
__device__ float g_H    [MROWS * DD];
__device__ float g_Qb   [MROWS * DD];
__device__ float g_Kb   [MROWS * DD];
__device__ float g_Vb   [MROWS * DD];
__device__ float g_Ab   [MROWS * DD];
__device__ float g_x    [NSEQ * DD];

// ---------------- helpers ----------------------------------------------------
__device__ __forceinline__ uint32_t pack_bf16x2(float lo, float hi) {
    __nv_bfloat162 p = __floats2bfloat162_rn(lo, hi);   // p.x = lo, p.y = hi
    uint32_t r;
    memcpy(&r, &p, 4);
    return r;
}

__device__ __forceinline__ void mma_bf16(float& d0, float& d1, float& d2, float& d3,
                                         uint32_t a0, uint32_t a1, uint32_t a2, uint32_t a3,
                                         uint32_t b0, uint32_t b1) {
    asm volatile("mma.sync.aligned.m16n8k16.row.col.f32.bf16.bf16.f32 "
                 "{%0,%1,%2,%3}, {%4,%5,%6,%7}, {%8,%9}, {%0,%1,%2,%3};"
                 : "+f"(d0), "+f"(d1), "+f"(d2), "+f"(d3)
                 : "r"(a0), "r"(a1), "r"(a2), "r"(a3), "r"(b0), "r"(b1));
}

__device__ __forceinline__ bool better(float v1, int i1, float v2, int i2) {
    return (v1 > v2) || (v1 == v2 && i1 < i2);   // jax top_k tie-break
}
__device__ __forceinline__ void ins3(float v, int i,
                                     float& v0, int& i0, float& v1, int& i1,
                                     float& v2, int& i2) {
    if (better(v, i, v2, i2)) {
        if (better(v, i, v1, i1)) {
            v2 = v1; i2 = i1;
            if (better(v, i, v0, i0)) { v1 = v0; i1 = i0; v0 = v; i0 = i; }
            else                      { v1 = v;  i1 = i; }
        } else { v2 = v; i2 = i; }
    }
}
__device__ __forceinline__ void ins4(float v, int i,
                                     float& t0, int& i0, float& t1, int& i1,
                                     float& t2, int& i2, float& t3, int& i3) {
    if (v <= t3) return;
    if (v > t1) {
        if (v > t0) { t3 = t2; i3 = i2; t2 = t1; i2 = i1; t1 = t0; i1 = i0; t0 = v; i0 = i; }
        else        { t3 = t2; i3 = i2; t2 = t1; i2 = i1; t1 = v;  i1 = i; }
    } else {
        if (v > t2) { t3 = t2; i3 = i2; t2 = v; i2 = i; }
        else        { t3 = v;  i3 = i; }
    }
}

// ---------------- kernel 1: normalize queries (+ bf16 copy) ------------------
__global__ void normalize_kernel(const float* __restrict__ q) {
    __shared__ float ws[8];
    int b = blockIdx.x, t = threadIdx.x;
    float v = q[b * DD + t];
    float s = v * v;
    #pragma unroll
    for (int o = 16; o; o >>= 1) s += __shfl_xor_sync(0xffffffffu, s, o);
    if ((t & 31) == 0) ws[t >> 5] = s;
    __syncthreads();
    float tot = 0.f;
    #pragma unroll
    for (int w = 0; w < 8; w++) tot += ws[w];
    float qn = v / sqrtf(tot);
    g_qn [b * DD + t] = qn;
    g_qhi[b * DD + t] = __float2bfloat16(qn);
}

// ---------------- kernel 2: fused sims (fp32 load -> bf16 frag -> mma.sync) --
// 148 CTAs x 512 threads (16 warps). Warp w owns q rows [16w, 16w+16).
// Per tile (32 cols x 256 d): each thread LDG.128s two adjacent d-rows
// (d even, d+1) at 4 n-positions, packs 4 bf16x2, STS into fragment layout:
//   frag uint4 index f = (Tloc*8 + ks2)*32 + lane,
//   lane = ((n&7)<<2) | ((d&7)>>1),  rr = ((d>>4)&1)<<1 | ((d>>3)&1),
//   ks2 = d>>5, Tloc = n>>3.   (Layout proven bit-exact in R10.)
__global__ void __launch_bounds__(512, 1) sims_mma_kernel(const float* __restrict__ w) {
    __shared__ uint4 sB[2][1024];
    const int tid = threadIdx.x;
    const int wid = tid >> 5, lane = tid & 31;
    const int g = lane >> 2, qk = lane & 3;
    const int bx = blockIdx.x;
    const int row0 = wid * 16 + g;

    // ---- persistent A fragments: 16 ksteps x 4 regs ----
    uint32_t Af[16][4];
    const uint32_t* qh = (const uint32_t*)g_qhi;
    #pragma unroll
    for (int ks = 0; ks < 16; ks++) {
        int k0 = ks * 16 + qk * 2;
        Af[ks][0] = qh[(row0 * DD + k0) >> 1];
        Af[ks][1] = qh[((row0 + 8) * DD + k0) >> 1];
        Af[ks][2] = qh[(row0 * DD + k0 + 8) >> 1];
        Af[ks][3] = qh[((row0 + 8) * DD + k0 + 8) >> 1];
    }

    const int ntiles = (NCHUNK - bx + NCTA - 1) / NCTA;

    float va0 = -FLT_MAX, va1 = -FLT_MAX, va2 = -FLT_MAX, va3 = -FLT_MAX;
    int   ja0 = 0x7fffffff, ja1 = 0x7fffffff, ja2 = 0x7fffffff, ja3 = 0x7fffffff;
    float vb0 = -FLT_MAX, vb1 = -FLT_MAX, vb2 = -FLT_MAX, vb3 = -FLT_MAX;
    int   jb0 = 0x7fffffff, jb1 = 0x7fffffff, jb2 = 0x7fffffff, jb3 = 0x7fffffff;

    // prefetch registers: 2 assignments x 2 d-rows, float4 each
    float4 pf[4];

    auto ldg_tile = [&](int tile) {
        const size_t col0 = (size_t)tile * 32;
        #pragma unroll
        for (int p = 0; p < 2; p++) {
            int u = tid + p * 512;
            int d  = (u >> 3) * 2;
            int n4 = (u & 7) * 4;
            const float* base = w + (size_t)d * NN + col0 + n4;
            pf[p * 2]     = *(const float4*)(base);
            pf[p * 2 + 1] = *(const float4*)(base + NN);
        }
    };
    auto sts_tile = [&](int buf) {
        uint32_t* dst = (uint32_t*)&sB[buf][0];
        #pragma unroll
        for (int p = 0; p < 2; p++) {
            int u = tid + p * 512;
            int d  = (u >> 3) * 2;
            int n4 = (u & 7) * 4;
            const int ks2 = d >> 5;
            const int rr = (((d >> 4) & 1) << 1) | ((d >> 3) & 1);
            const int lane_lo = (d & 7) >> 1;
            const float* a = (const float*)&pf[p * 2];
            const float* b = (const float*)&pf[p * 2 + 1];
            #pragma unroll
            for (int i = 0; i < 4; i++) {
                int nl = n4 + i;
                int lane2 = ((nl & 7) << 2) | lane_lo;
                int f = ((nl >> 3) * 8 + ks2) * 32 + lane2;
                dst[f * 4 + rr] = pack_bf16x2(a[i], b[i]);
            }
        }
    };

    ldg_tile(bx);   // prologue

    for (int t = 0; t < ntiles; t++) {
        const int buf = t & 1;
        sts_tile(buf);
        __syncthreads();
        if (t + 1 < ntiles) ldg_tile(bx + (t + 1) * NCTA);

        const int colbase = (bx + t * NCTA) * 32 + qk * 2;
        #pragma unroll
        for (int nt = 0; nt < 4; nt++) {
            float d0 = 0.f, d1 = 0.f, d2 = 0.f, d3 = 0.f;
            #pragma unroll
            for (int ks2 = 0; ks2 < 8; ks2++) {
                uint4 bf = sB[buf][(nt * 8 + ks2) * 32 + lane];
                mma_bf16(d0, d1, d2, d3,
                         Af[2*ks2][0], Af[2*ks2][1], Af[2*ks2][2], Af[2*ks2][3],
                         bf.x, bf.y);
                mma_bf16(d0, d1, d2, d3,
                         Af[2*ks2+1][0], Af[2*ks2+1][1], Af[2*ks2+1][2], Af[2*ks2+1][3],
                         bf.z, bf.w);
            }
            int c0 = colbase + nt * 8;
            ins4(d0, c0,     va0, ja0, va1, ja1, va2, ja2, va3, ja3);
            ins4(d1, c0 + 1, va0, ja0, va1, ja1, va2, ja2, va3, ja3);
            ins4(d2, c0,     vb0, jb0, vb1, jb1, vb2, jb2, vb3, jb3);
            ins4(d3, c0 + 1, vb0, jb0, vb1, jb1, vb2, jb2, vb3, jb3);
        }
        __syncthreads();   // all warps done with sB[buf] before next sts_tile
    }

    // ---- merge top-4 across the 4 lanes of each quad (width-4 butterflies) --
    #pragma unroll
    for (int m = 1; m <= 2; m <<= 1) {
        float r0 = __shfl_xor_sync(0xffffffffu, va0, m, 4);
        float r1 = __shfl_xor_sync(0xffffffffu, va1, m, 4);
        float r2 = __shfl_xor_sync(0xffffffffu, va2, m, 4);
        float r3 = __shfl_xor_sync(0xffffffffu, va3, m, 4);
        int   s0 = __shfl_xor_sync(0xffffffffu, ja0, m, 4);
        int   s1 = __shfl_xor_sync(0xffffffffu, ja1, m, 4);
        int   s2 = __shfl_xor_sync(0xffffffffu, ja2, m, 4);
        int   s3 = __shfl_xor_sync(0xffffffffu, ja3, m, 4);
        ins4(r0, s0, va0, ja0, va1, ja1, va2, ja2, va3, ja3);
        ins4(r1, s1, va0, ja0, va1, ja1, va2, ja2, va3, ja3);
        ins4(r2, s2, va0, ja0, va1, ja1, va2, ja2, va3, ja3);
        ins4(r3, s3, va0, ja0, va1, ja1, va2, ja2, va3, ja3);
        r0 = __shfl_xor_sync(0xffffffffu, vb0, m, 4);
        r1 = __shfl_xor_sync(0xffffffffu, vb1, m, 4);
        r2 = __shfl_xor_sync(0xffffffffu, vb2, m, 4);
        r3 = __shfl_xor_sync(0xffffffffu, vb3, m, 4);
        s0 = __shfl_xor_sync(0xffffffffu, jb0, m, 4);
        s1 = __shfl_xor_sync(0xffffffffu, jb1, m, 4);
        s2 = __shfl_xor_sync(0xffffffffu, jb2, m, 4);
        s3 = __shfl_xor_sync(0xffffffffu, jb3, m, 4);
        ins4(r0, s0, vb0, jb0, vb1, jb1, vb2, jb2, vb3, jb3);
        ins4(r1, s1, vb0, jb0, vb1, jb1, vb2, jb2, vb3, jb3);
        ins4(r2, s2, vb0, jb0, vb1, jb1, vb2, jb2, vb3, jb3);
        ins4(r3, s3, vb0, jb0, vb1, jb1, vb2, jb2, vb3, jb3);
    }
    if (qk == 0) {
        int base = row0 * NCAND + bx * 4;
        g_pv[base + 0] = va0; g_pi[base + 0] = ja0;
        g_pv[base + 1] = va1; g_pi[base + 1] = ja1;
        g_pv[base + 2] = va2; g_pi[base + 2] = ja2;
        g_pv[base + 3] = va3; g_pi[base + 3] = ja3;
        base = (row0 + 8) * NCAND + bx * 4;
        g_pv[base + 0] = vb0; g_pi[base + 0] = jb0;
        g_pv[base + 1] = vb1; g_pi[base + 1] = jb1;
        g_pv[base + 2] = vb2; g_pi[base + 2] = jb2;
        g_pv[base + 3] = vb3; g_pi[base + 3] = jb3;
    }
}

// ---------------- kernel 3: parallel merge + exact rescore + top-3 ----------
// 256 threads. 8 warps each sieve a 74-candidate span to top-4 (any true
// top-3 survives: at most 2 candidates globally beat it). Union of 32
// candidates rescored exactly in fp32 (8 threads/cand), thread0 final top-3.
__global__ void merge_rescore_kernel(const float* __restrict__ w,
                                     const int* __restrict__ label) {
    __shared__ float cv[NCAND];
    __shared__ int   ci[NCAND];
    __shared__ float qrow[DD];
    __shared__ float c32v[32];
    __shared__ int   c32i[32];
    __shared__ float exv[32];
    int q = blockIdx.x, t = threadIdx.x;
    int wid = t >> 5, lane = t & 31;
    qrow[t] = g_qn[q * DD + t];
    for (int j = t; j < NCAND; j += 256) {
        cv[j] = g_pv[q * NCAND + j];
        ci[j] = g_pi[q * NCAND + j];
    }
    __syncthreads();

    // per-warp top-4 over span [wid*74, wid*74+74)
    float t0 = -FLT_MAX, t1 = -FLT_MAX, t2 = -FLT_MAX, t3 = -FLT_MAX;
    int   i0 = 0x7fffffff, i1 = 0x7fffffff, i2 = 0x7fffffff, i3 = 0x7fffffff;
    const int lo = wid * 74, hi = lo + 74;
    for (int j = lo + lane; j < hi; j += 32)
        ins4(cv[j], ci[j], t0, i0, t1, i1, t2, i2, t3, i3);
    #pragma unroll
    for (int m = 16; m >= 1; m >>= 1) {
        float r0 = __shfl_xor_sync(0xffffffffu, t0, m);
        float r1 = __shfl_xor_sync(0xffffffffu, t1, m);
        float r2 = __shfl_xor_sync(0xffffffffu, t2, m);
        float r3 = __shfl_xor_sync(0xffffffffu, t3, m);
        int   s0 = __shfl_xor_sync(0xffffffffu, i0, m);
        int   s1 = __shfl_xor_sync(0xffffffffu, i1, m);
        int   s2 = __shfl_xor_sync(0xffffffffu, i2, m);
        int   s3 = __shfl_xor_sync(0xffffffffu, i3, m);
        ins4(r0, s0, t0, i0, t1, i1, t2, i2, t3, i3);
        ins4(r1, s1, t0, i0, t1, i1, t2, i2, t3, i3);
        ins4(r2, s2, t0, i0, t1, i1, t2, i2, t3, i3);
        ins4(r3, s3, t0, i0, t1, i1, t2, i2, t3, i3);
    }
    if (lane == 0) {
        c32v[wid * 4 + 0] = t0; c32i[wid * 4 + 0] = i0;
        c32v[wid * 4 + 1] = t1; c32i[wid * 4 + 1] = i1;
        c32v[wid * 4 + 2] = t2; c32i[wid * 4 + 2] = i2;
        c32v[wid * 4 + 3] = t3; c32i[wid * 4 + 3] = i3;
    }
    __syncthreads();

    // exact rescore: candidate c = t>>3, 8 threads x 32 d each
    {
        int c = t >> 3, sub = t & 7;
        int idx = c32i[c];
        float acc = 0.f;
        #pragma unroll
        for (int dd = 0; dd < 32; dd++) {
            int d = sub * 32 + dd;
            acc += qrow[d] * w[(size_t)d * NN + idx];
        }
        #pragma unroll
        for (int m = 4; m >= 1; m >>= 1)
            acc += __shfl_xor_sync(0xffffffffu, acc, m, 8);
        if (sub == 0) exv[c] = acc;
    }
    __syncthreads();

    if (t == 0) {
        float f0 = -FLT_MAX, f1 = -FLT_MAX, f2 = -FLT_MAX;
        int   j0 = 0x7fffffff, j1 = 0x7fffffff, j2 = 0x7fffffff;
        for (int k = 0; k < 32; k++)
            ins3(exv[k], c32i[k], f0, j0, f1, j1, f2, j2);
        g_score[q * 3 + 0] = f0; g_idx[q * 3 + 0] = j0; g_lab[q * 3 + 0] = label[j0];
        g_score[q * 3 + 1] = f1; g_idx[q * 3 + 1] = j1; g_lab[q * 3 + 1] = label[j1];
        g_score[q * 3 + 2] = f2; g_idx[q * 3 + 2] = j2; g_lab[q * 3 + 2] = label[j2];
    }
}

// ---------------- kernel 4: build H (gather) ---------------------------------
__global__ void build_h_kernel(const float* __restrict__ queries,
                               const float* __restrict__ w) {
    int s = blockIdx.x, d = threadIdx.x;
    int b = s / KK;
    int lab = g_lab[s];
    float score = g_score[s];
    int idx = g_idx[s];
    float* Hrow = &g_H[s * 3 * DD];
    Hrow[d]          = (d == lab) ? score : 0.f;
    Hrow[DD + d]     = queries[b * DD + d];
    Hrow[2 * DD + d] = w[(size_t)d * NN + idx];
}

// ---------------- tail (proven) ----------------------------------------------
__global__ void qkv_kernel(const float* __restrict__ Wq, const float* __restrict__ bq,
                           const float* __restrict__ Wk, const float* __restrict__ bk,
                           const float* __restrict__ Wv, const float* __restrict__ bv) {
    __shared__ float h[16][DD];
    int r0 = blockIdx.x * 16, t = threadIdx.x;
    #pragma unroll
    for (int i = 0; i < 16; i++) h[i][t] = g_H[(r0 + i) * DD + t];
    __syncthreads();
    float aq[16], ak[16], av[16];
    #pragma unroll
    for (int i = 0; i < 16; i++) { aq[i] = bq[t]; ak[i] = bk[t]; av[i] = bv[t]; }
    for (int d = 0; d < DD; d++) {
        float wq = Wq[d * DD + t], wk = Wk[d * DD + t], wv = Wv[d * DD + t];
        #pragma unroll
        for (int i = 0; i < 16; i++) {
            float hv = h[i][d];
            aq[i] += hv * wq; ak[i] += hv * wk; av[i] += hv * wv;
        }
    }
    #pragma unroll
    for (int i = 0; i < 16; i++) {
        g_Qb[(r0 + i) * DD + t] = aq[i];
        g_Kb[(r0 + i) * DD + t] = ak[i];
        g_Vb[(r0 + i) * DD + t] = av[i];
    }
}

__global__ void attn_kernel() {
    __shared__ float q[3][DD], k[3][DD], v[3][DD], a[9];
    int s = blockIdx.x, t = threadIdx.x;
    int base = s * 3 * DD;
    #pragma unroll
    for (int i = 0; i < 3; i++) {
        q[i][t] = g_Qb[base + i * DD + t];
        k[i][t] = g_Kb[base + i * DD + t];
        v[i][t] = g_Vb[base + i * DD + t];
    }
    __syncthreads();
    if (t < 9) {
        int i = t / 3, j = t % 3;
        float acc = 0.f;
        for (int d = 0; d < DD; d++) acc += q[i][d] * k[j][d];
        a[t] = acc * 0.125f;
    }
    __syncthreads();
    if (t < 3) {
        float m0 = fmaxf(a[t*3], fmaxf(a[t*3+1], a[t*3+2]));
        float e0 = expf(a[t*3] - m0), e1 = expf(a[t*3+1] - m0), e2 = expf(a[t*3+2] - m0);
        float inv = 1.f / (e0 + e1 + e2);
        a[t*3] = e0 * inv; a[t*3+1] = e1 * inv; a[t*3+2] = e2 * inv;
    }
    __syncthreads();
    #pragma unroll
    for (int i = 0; i < 3; i++)
        g_Ab[base + i * DD + t] = a[i*3] * v[0][t] + a[i*3+1] * v[1][t] + a[i*3+2] * v[2][t];
}

__global__ void oproj_kernel(const float* __restrict__ Wo, const float* __restrict__ bo) {
    __shared__ float h[16][DD];
    int r0 = blockIdx.x * 16, t = threadIdx.x;
    #pragma unroll
    for (int i = 0; i < 16; i++) h[i][t] = g_Ab[(r0 + i) * DD + t];
    __syncthreads();
    float ao[16];
    #pragma unroll
    for (int i = 0; i < 16; i++) ao[i] = bo[t];
    for (int d = 0; d < DD; d++) {
        float wo = Wo[d * DD + t];
        #pragma unroll
        for (int i = 0; i < 16; i++) ao[i] += h[i][d] * wo;
    }
    #pragma unroll
    for (int i = 0; i < 16; i++) g_H[(r0 + i) * DD + t] = ao[i];
}

__global__ void dense_kernel(const float* __restrict__ W, const float* __restrict__ b) {
    __shared__ float h[DD];
    int s = blockIdx.x, t = threadIdx.x;
    h[t] = g_H[s * 3 * DD + t];
    __syncthreads();
    float acc = b[t];
    for (int d = 0; d < DD; d++) acc += h[d] * W[d * DD + t];
    g_x[s * DD + t] = tanhf(acc);
}

__global__ void final_kernel(const float* __restrict__ out_w,
                             const float* __restrict__ out_b,
                             float* __restrict__ out) {
    __shared__ float lg[36];
    int b = blockIdx.x, t = threadIdx.x;
    int k = t / NLAB, l = t % NLAB;
    float acc = out_b[l];
    const float* x = &g_x[(b * 3 + k) * DD];
    for (int d = 0; d < DD; d++) acc += x[d] * out_w[d * NLAB + l];
    lg[t] = acc;
    __syncthreads();
    if (t < NLAB) {
        float mean = (lg[t] + lg[NLAB + t] + lg[2 * NLAB + t]) * (1.f / 3.f);
        int l0 = g_lab[b * 3], l1 = g_lab[b * 3 + 1], l2 = g_lab[b * 3 + 2];
        float cnt = (float)((l0 == t) + (l1 == t) + (l2 == t));
        out[b * NLAB + t] = 0.5f * mean + 0.5f * (cnt * (1.f / 3.f));
    }
}

// ---------------- launcher ---------------------------------------------------
extern "C" void kernel_launch(void* const* d_in, const int* in_sizes, int n_in,
                              void* d_out, int out_size) {
    const float* queries = (const float*)d_in[0];
    const float* weight  = (const float*)d_in[1];
    const int*   label   = (const int*)  d_in[2];
    const float* Wq      = (const float*)d_in[3];
    const float* bq      = (const float*)d_in[4];
    const float* Wk      = (const float*)d_in[5];
    const float* bk      = (const float*)d_in[6];
    const float* Wv      = (const float*)d_in[7];
    const float* bv      = (const float*)d_in[8];
    const float* Wo      = (const float*)d_in[9];
    const float* bo      = (const float*)d_in[10];
    const float* dense_w = (const float*)d_in[11];
    const float* dense_b = (const float*)d_in[12];
    const float* out_w   = (const float*)d_in[13];
    const float* out_b   = (const float*)d_in[14];
    float* out = (float*)d_out;

    normalize_kernel<<<BB, DD>>>(queries);
    sims_mma_kernel<<<NCTA, 512>>>(weight);
    merge_rescore_kernel<<<BB, 256>>>(weight, label);
    build_h_kernel<<<NSEQ, DD>>>(queries, weight);

    for (int l = 0; l < 2; l++) {
        qkv_kernel<<<MROWS / 16, DD>>>(Wq + l * DD * DD, bq + l * DD,
                                       Wk + l * DD * DD, bk + l * DD,
                                       Wv + l * DD * DD, bv + l * DD);
        attn_kernel<<<NSEQ, DD>>>();
        oproj_kernel<<<MROWS / 16, DD>>>(Wo + l * DD * DD, bo + l * DD);
    }
    dense_kernel<<<NSEQ, DD>>>(dense_w, dense_b);
    final_kernel<<<BB, 36>>>(out_w, out_b, out);
}